// round 8
// baseline (speedup 1.0000x reference)
#include <cuda_runtime.h>
#include <cuda_fp16.h>
#include <cstdint>
#include <math.h>

#define TOKENS 36864
#define PS 768
#define HID 1536

#define BM 128
#define BN 128
#define BKH 64                 // K halves per stage (128 B rows)
#define NST 3
#define ROWB 128
#define STAGE_BYTES ((BM + BN) * ROWB)        // 32768
#define SMEM_BYTES (NST * STAGE_BYTES)        // 98304

// Scratch (device globals — allocation guards forbid cudaMalloc)
__device__ __half g_Y[(size_t)TOKENS * PS];     // LN'd patches, fp16, k-permuted
__device__ __half g_H[(size_t)TOKENS * HID];    // hidden acts, fp16, k-permuted
__device__ __half g_W1T[(size_t)HID * PS];      // w1^T [1536,768], k-permuted
__device__ __half g_W2T[(size_t)PS * HID];      // w2^T [768,1536], k-permuted

// k-permutation within 32-blocks: k=(q,h,t,i) -> pos = t*8 + q*4 + h*2 + i
__device__ __forceinline__ int permk32(int k) {
    return (k & ~31) | ((k & 6) << 2) | (((k >> 4) & 1) << 2)
         | (((k >> 3) & 1) << 1) | (k & 1);
}
__device__ __forceinline__ uint32_t smem_u32(const void* p) {
    uint32_t a;
    asm("{ .reg .u64 t; cvta.to.shared.u64 t, %1; cvt.u32.u64 %0, t; }" : "=r"(a) : "l"(p));
    return a;
}
__device__ __forceinline__ void cp_async16(uint32_t dst, const void* src) {
    asm volatile("cp.async.cg.shared.global [%0], [%1], 16;\n" :: "r"(dst), "l"(src));
}
__device__ __forceinline__ void cp_commit() { asm volatile("cp.async.commit_group;\n" ::: "memory"); }
__device__ __forceinline__ void cp_wait1()  { asm volatile("cp.async.wait_group 1;\n" ::: "memory"); }
__device__ __forceinline__ void cp_wait0()  { asm volatile("cp.async.wait_group 0;\n" ::: "memory"); }

__device__ __forceinline__ void mma_f16(float* d, uint32_t a0, uint32_t a1,
                                        uint32_t a2, uint32_t a3,
                                        uint32_t b0, uint32_t b1) {
    asm volatile(
        "mma.sync.aligned.m16n8k16.row.col.f32.f16.f16.f32 "
        "{%0,%1,%2,%3}, {%4,%5,%6,%7}, {%8,%9}, {%0,%1,%2,%3};"
        : "+f"(d[0]), "+f"(d[1]), "+f"(d[2]), "+f"(d[3])
        : "r"(a0), "r"(a1), "r"(a2), "r"(a3), "r"(b0), "r"(b1));
}

// Fast exact GELU: 0.5x(1+erf(x/sqrt2)), erf via A&S 7.1.26 (|err|<=1.5e-7)
__device__ __forceinline__ float gelu_fast(float v) {
    const float z = fabsf(v) * 0.70710678118654752f;
    const float t = __fdividef(1.0f, fmaf(0.3275911f, z, 1.0f));
    float p = fmaf(t, 1.061405429f, -1.453152027f);
    p = fmaf(t, p, 1.421413741f);
    p = fmaf(t, p, -0.284496736f);
    p = fmaf(t, p, 0.254829592f);
    p *= t;
    const float e = __expf(-z * z);
    const float erfa = fmaf(-p, e, 1.0f);          // erf(|z|)
    const float erfv = copysignf(erfa, v);
    return 0.5f * v * (1.0f + erfv);
}

// ---------------------------------------------------------------------------
// Kernel 1: unfold + LayerNorm -> fp16, k-permuted
// ---------------------------------------------------------------------------
__global__ void patch_ln_kernel(const float* __restrict__ x,
                                const float* __restrict__ ln_w,
                                const float* __restrict__ ln_b) {
    const int token = blockIdx.x;
    const int b  = token / 576;
    const int l  = token - b * 576;
    const int hp = l / 24;
    const int wp = l - hp * 24;
    const int t  = threadIdx.x;

    float v[3];
#pragma unroll
    for (int i = 0; i < 3; ++i) {
        const int p   = t + i * 256;
        const int c   = p >> 8;
        const int rem = p & 255;
        const int ph  = rem >> 4;
        const int pw  = rem & 15;
        const int xi  = ((b * 3 + c) * 384 + hp * 16 + ph) * 384 + wp * 16 + pw;
        v[i] = x[xi];
    }
    float s  = v[0] + v[1] + v[2];
    float sq = v[0] * v[0] + v[1] * v[1] + v[2] * v[2];
#pragma unroll
    for (int o = 16; o > 0; o >>= 1) {
        s  += __shfl_xor_sync(0xffffffffu, s, o);
        sq += __shfl_xor_sync(0xffffffffu, sq, o);
    }
    __shared__ float red_s[8], red_q[8];
    const int warp = t >> 5, lane = t & 31;
    if (lane == 0) { red_s[warp] = s; red_q[warp] = sq; }
    __syncthreads();
    float tot = 0.f, totq = 0.f;
#pragma unroll
    for (int i = 0; i < 8; ++i) { tot += red_s[i]; totq += red_q[i]; }
    const float mu  = tot * (1.0f / 768.0f);
    const float var = totq * (1.0f / 768.0f) - mu * mu;
    const float inv = rsqrtf(var + 1e-5f);

    __half* yrow = g_Y + (size_t)token * PS;
#pragma unroll
    for (int i = 0; i < 3; ++i) {
        const int p = t + i * 256;
        yrow[permk32(p)] = __float2half_rn((v[i] - mu) * inv * ln_w[p] + ln_b[p]);
    }
}

// ---------------------------------------------------------------------------
// Transpose: src [R,C] fp32 -> dst [C,R] fp16, K dim (rows of dst) permuted
// ---------------------------------------------------------------------------
template <int WHICH>
__global__ void transpose_kernel(const float* __restrict__ src, int R, int C) {
    __half* __restrict__ dst = (WHICH == 0) ? g_W1T : g_W2T;
    __shared__ float t[32][33];
    const int bx = blockIdx.x * 32, by = blockIdx.y * 32;
    const int x = threadIdx.x, y = threadIdx.y;
#pragma unroll
    for (int i = 0; i < 32; i += 8)
        t[y + i][x] = src[(size_t)(by + y + i) * C + bx + x];
    __syncthreads();
#pragma unroll
    for (int i = 0; i < 32; i += 8)
        dst[(size_t)(bx + y + i) * R + permk32(by + x)] = __float2half_rn(t[x][y + i]);
}

// ---------------------------------------------------------------------------
// FP16 mma.sync GEMM: CTA 128x128, 8 warps (2m x 4n), warp tile 64x32,
// m16n8k16. BK=64, 3-stage cp.async (wait1), ADD-swizzled smem, LDS.128.
// EPI 0: C = fp16(gelu(C+bias)) -> g_H (k-permuted cols)
// EPI 1: C = C+bias, fold + residual x -> out (fp32)
// ---------------------------------------------------------------------------
template <int NGL, int K, int EPI>
__global__ __launch_bounds__(256, 2) void mma_gemm_kernel(
        const float* __restrict__ bias,
        const float* __restrict__ x,
        float* __restrict__ out) {
    extern __shared__ char smem[];
    const __half* __restrict__ A  = (EPI == 0) ? g_Y : g_H;
    const __half* __restrict__ Bt = (EPI == 0) ? g_W1T : g_W2T;

    const int tid  = threadIdx.x;
    const int lane = tid & 31;
    const int wid  = tid >> 5;
    const int wm   = wid & 1;
    const int wn   = wid >> 1;
    const int g    = lane >> 2;
    const int tig  = lane & 3;
    const int mBase = blockIdx.y * BM;
    const int nBase = blockIdx.x * BN;

    const uint32_t sbase = smem_u32(smem);

    // cp.async: A 1024 + B 1024 chunks (16B) per stage; 8 per thread
    const int r0 = tid >> 3;       // base row 0..31 (parity const as r += 32)
    const int j0 = tid & 7;        // source chunk within 128B k-row
    const __half* gA0 = A  + (size_t)(mBase + r0) * K + j0 * 8;
    const __half* gB0 = Bt + (size_t)(nBase + r0) * K + j0 * 8;
    const uint32_t dchunk = (uint32_t)((j0 + 4 * (r0 & 1)) & 7);
    const uint32_t dA0 = (uint32_t)r0 * ROWB + dchunk * 16u;

    auto load_stage = [&](int slot, int ks) {
        const uint32_t sb = sbase + (uint32_t)slot * STAGE_BYTES;
        const int ko = ks * BKH;
#pragma unroll
        for (int i = 0; i < 4; ++i)
            cp_async16(sb + dA0 + i * (32u * ROWB), gA0 + (size_t)(32 * i) * K + ko);
#pragma unroll
        for (int i = 0; i < 4; ++i)
            cp_async16(sb + (uint32_t)(BM * ROWB) + dA0 + i * (32u * ROWB),
                       gB0 + (size_t)(32 * i) * K + ko);
        cp_commit();
    };

    float acc[4][4][4];
#pragma unroll
    for (int i = 0; i < 4; ++i)
#pragma unroll
        for (int j = 0; j < 4; ++j)
#pragma unroll
            for (int q = 0; q < 4; ++q) acc[i][j][q] = 0.f;

    // fragment read offsets: phys chunk = (qq*4 + tig + 4*(g&1)) & 7
    const int pa = g & 1;
    uint32_t ckq[2];
#pragma unroll
    for (int qq = 0; qq < 2; ++qq)
        ckq[qq] = (uint32_t)(((qq * 4 + tig + 4 * pa) & 7) * 16);
    const uint32_t aRow0 = (uint32_t)(wm * 64 + g) * ROWB;
    const uint32_t bRow0 = (uint32_t)(BM * ROWB) + (uint32_t)(wn * 32 + g) * ROWB;

    constexpr int KT = K / BKH;
    load_stage(0, 0);
    load_stage(1, 1);

#pragma unroll 3
    for (int kt = 0; kt < KT; ++kt) {
        if (kt + 1 < KT) cp_wait1(); else cp_wait0();
        __syncthreads();
        if (kt + 2 < KT) load_stage((kt + 2) % NST, kt + 2);

        const char* st = smem + (kt % NST) * STAGE_BYTES;
#pragma unroll
        for (int qq = 0; qq < 2; ++qq) {
            uint4 alo[4], ahi[4], bb[4];
#pragma unroll
            for (int mt = 0; mt < 4; ++mt) {
                alo[mt] = *(const uint4*)(st + aRow0 + (uint32_t)(mt * 16) * ROWB + ckq[qq]);
                ahi[mt] = *(const uint4*)(st + aRow0 + (uint32_t)(mt * 16 + 8) * ROWB + ckq[qq]);
            }
#pragma unroll
            for (int nt = 0; nt < 4; ++nt)
                bb[nt] = *(const uint4*)(st + bRow0 + (uint32_t)(nt * 8) * ROWB + ckq[qq]);
#pragma unroll
            for (int mt = 0; mt < 4; ++mt)
#pragma unroll
                for (int nt = 0; nt < 4; ++nt) {
                    mma_f16(acc[mt][nt], alo[mt].x, ahi[mt].x, alo[mt].y, ahi[mt].y,
                            bb[nt].x, bb[nt].y);
                    mma_f16(acc[mt][nt], alo[mt].z, ahi[mt].z, alo[mt].w, ahi[mt].w,
                            bb[nt].z, bb[nt].w);
                }
        }
    }

    // ---------------- epilogue (hoisted per-nt invariants) ----------------
    int   pcol[4];       // EPI0: permuted col offset; EPI1: image col offset
    float2 bv[4];
#pragma unroll
    for (int nt = 0; nt < 4; ++nt) {
        const int col = nBase + wn * 32 + nt * 8 + 2 * tig;
        bv[nt] = make_float2(__ldg(&bias[col]), __ldg(&bias[col + 1]));
        if (EPI == 0) {
            pcol[nt] = permk32(col);
        } else {
            const int cg  = col >> 8;
            const int rem = col & 255;
            const int ph  = rem >> 4;
            const int pw  = rem & 15;
            pcol[nt] = cg * 147456 + ph * 384 + pw;   // cg*384*384 + ph*384 + pw
        }
    }

#pragma unroll
    for (int mt = 0; mt < 4; ++mt) {
#pragma unroll
        for (int half = 0; half < 2; ++half) {
            const int row = mBase + wm * 64 + mt * 16 + g + half * 8;
            if (EPI == 0) {
                __half* hrow = g_H + (size_t)row * NGL;
#pragma unroll
                for (int nt = 0; nt < 4; ++nt) {
                    const float a0 = gelu_fast(acc[mt][nt][half * 2 + 0] + bv[nt].x);
                    const float a1 = gelu_fast(acc[mt][nt][half * 2 + 1] + bv[nt].y);
                    *(__half2*)(hrow + pcol[nt]) = __floats2half2_rn(a0, a1);
                }
            } else {
                const int bimg = row / 576;
                const int l    = row - bimg * 576;
                const int hp   = l / 24;
                const int wp   = l - hp * 24;
                const size_t rowOff = (size_t)bimg * 442368 + hp * 6144 + wp * 16;
#pragma unroll
                for (int nt = 0; nt < 4; ++nt) {
                    const size_t oi = rowOff + (size_t)pcol[nt];
                    const float2 xv = *(const float2*)(x + oi);
                    float2 v;
                    v.x = xv.x + acc[mt][nt][half * 2 + 0] + bv[nt].x;
                    v.y = xv.y + acc[mt][nt][half * 2 + 1] + bv[nt].y;
                    *(float2*)(out + oi) = v;
                }
            }
        }
    }
}

extern "C" void kernel_launch(void* const* d_in, const int* in_sizes, int n_in,
                              void* d_out, int out_size) {
    const float* x    = (const float*)d_in[0];
    const float* ln_w = (const float*)d_in[1];
    const float* ln_b = (const float*)d_in[2];
    const float* w1   = (const float*)d_in[3];
    const float* b1   = (const float*)d_in[4];
    const float* w2   = (const float*)d_in[5];
    const float* b2   = (const float*)d_in[6];
    float* out        = (float*)d_out;

    static bool configured = false;
    if (!configured) {
        cudaFuncSetAttribute(mma_gemm_kernel<HID, PS, 0>,
                             cudaFuncAttributeMaxDynamicSharedMemorySize, SMEM_BYTES);
        cudaFuncSetAttribute(mma_gemm_kernel<PS, HID, 1>,
                             cudaFuncAttributeMaxDynamicSharedMemorySize, SMEM_BYTES);
        configured = true;
    }

    dim3 tb(32, 8);
    transpose_kernel<0><<<dim3(HID / 32, PS / 32), tb>>>(w1, PS, HID);
    transpose_kernel<1><<<dim3(PS / 32, HID / 32), tb>>>(w2, HID, PS);

    patch_ln_kernel<<<TOKENS, 256>>>(x, ln_w, ln_b);

    dim3 g1(HID / BN, TOKENS / BM);   // (12, 288)
    mma_gemm_kernel<HID, PS, 0><<<g1, 256, SMEM_BYTES>>>(b1, nullptr, nullptr);

    dim3 g2(PS / BN, TOKENS / BM);    // (6, 288)
    mma_gemm_kernel<PS, HID, 1><<<g2, 256, SMEM_BYTES>>>(b2, x, out);
}

// round 9
// speedup vs baseline: 1.0182x; 1.0182x over previous
#include <cuda_runtime.h>
#include <cuda_fp16.h>
#include <cstdint>
#include <math.h>

#define TOKENS 36864
#define PS 768
#define HID 1536

#define BM 128
#define BN 128
#define BKH 64                 // K halves per stage (128 B rows)
#define NST 3
#define ROWB 128
#define STAGE_BYTES ((BM + BN) * ROWB)        // 32768
#define SMEM_BYTES (NST * STAGE_BYTES)        // 98304

// Scratch (device globals — allocation guards forbid cudaMalloc)
__device__ __half g_Y[(size_t)TOKENS * PS];     // LN'd patches, fp16, k-permuted
__device__ __half g_H[(size_t)TOKENS * HID];    // hidden acts, fp16, k-permuted
__device__ __half g_W1T[(size_t)HID * PS];      // w1^T [1536,768], k-permuted
__device__ __half g_W2T[(size_t)PS * HID];      // w2^T [768,1536], k-permuted

// k-permutation within 32-blocks: k=(q,h,t,i) -> pos = t*8 + q*4 + h*2 + i
__device__ __forceinline__ int permk32(int k) {
    return (k & ~31) | ((k & 6) << 2) | (((k >> 4) & 1) << 2)
         | (((k >> 3) & 1) << 1) | (k & 1);
}
__device__ __forceinline__ uint32_t smem_u32(const void* p) {
    uint32_t a;
    asm("{ .reg .u64 t; cvta.to.shared.u64 t, %1; cvt.u32.u64 %0, t; }" : "=r"(a) : "l"(p));
    return a;
}
__device__ __forceinline__ void cp_async16(uint32_t dst, const void* src) {
    asm volatile("cp.async.cg.shared.global [%0], [%1], 16;\n" :: "r"(dst), "l"(src));
}
__device__ __forceinline__ void cp_commit() { asm volatile("cp.async.commit_group;\n" ::: "memory"); }
__device__ __forceinline__ void cp_wait1()  { asm volatile("cp.async.wait_group 1;\n" ::: "memory"); }
__device__ __forceinline__ void cp_wait0()  { asm volatile("cp.async.wait_group 0;\n" ::: "memory"); }

__device__ __forceinline__ void mma_f16(float* d, uint32_t a0, uint32_t a1,
                                        uint32_t a2, uint32_t a3,
                                        uint32_t b0, uint32_t b1) {
    asm volatile(
        "mma.sync.aligned.m16n8k16.row.col.f32.f16.f16.f32 "
        "{%0,%1,%2,%3}, {%4,%5,%6,%7}, {%8,%9}, {%0,%1,%2,%3};"
        : "+f"(d[0]), "+f"(d[1]), "+f"(d[2]), "+f"(d[3])
        : "r"(a0), "r"(a1), "r"(a2), "r"(a3), "r"(b0), "r"(b1));
}

// ---------------------------------------------------------------------------
// Kernel 1: unfold + LayerNorm -> fp16, k-permuted
// ---------------------------------------------------------------------------
__global__ void patch_ln_kernel(const float* __restrict__ x,
                                const float* __restrict__ ln_w,
                                const float* __restrict__ ln_b) {
    const int token = blockIdx.x;
    const int b  = token / 576;
    const int l  = token - b * 576;
    const int hp = l / 24;
    const int wp = l - hp * 24;
    const int t  = threadIdx.x;

    float v[3];
#pragma unroll
    for (int i = 0; i < 3; ++i) {
        const int p   = t + i * 256;
        const int c   = p >> 8;
        const int rem = p & 255;
        const int ph  = rem >> 4;
        const int pw  = rem & 15;
        const int xi  = ((b * 3 + c) * 384 + hp * 16 + ph) * 384 + wp * 16 + pw;
        v[i] = x[xi];
    }
    float s  = v[0] + v[1] + v[2];
    float sq = v[0] * v[0] + v[1] * v[1] + v[2] * v[2];
#pragma unroll
    for (int o = 16; o > 0; o >>= 1) {
        s  += __shfl_xor_sync(0xffffffffu, s, o);
        sq += __shfl_xor_sync(0xffffffffu, sq, o);
    }
    __shared__ float red_s[8], red_q[8];
    const int warp = t >> 5, lane = t & 31;
    if (lane == 0) { red_s[warp] = s; red_q[warp] = sq; }
    __syncthreads();
    float tot = 0.f, totq = 0.f;
#pragma unroll
    for (int i = 0; i < 8; ++i) { tot += red_s[i]; totq += red_q[i]; }
    const float mu  = tot * (1.0f / 768.0f);
    const float var = totq * (1.0f / 768.0f) - mu * mu;
    const float inv = rsqrtf(var + 1e-5f);

    __half* yrow = g_Y + (size_t)token * PS;
#pragma unroll
    for (int i = 0; i < 3; ++i) {
        const int p = t + i * 256;
        yrow[permk32(p)] = __float2half_rn((v[i] - mu) * inv * ln_w[p] + ln_b[p]);
    }
}

// ---------------------------------------------------------------------------
// Transpose: src [R,C] fp32 -> dst [C,R] fp16, K dim (rows of dst) permuted
// ---------------------------------------------------------------------------
template <int WHICH>
__global__ void transpose_kernel(const float* __restrict__ src, int R, int C) {
    __half* __restrict__ dst = (WHICH == 0) ? g_W1T : g_W2T;
    __shared__ float t[32][33];
    const int bx = blockIdx.x * 32, by = blockIdx.y * 32;
    const int x = threadIdx.x, y = threadIdx.y;
#pragma unroll
    for (int i = 0; i < 32; i += 8)
        t[y + i][x] = src[(size_t)(by + y + i) * C + bx + x];
    __syncthreads();
#pragma unroll
    for (int i = 0; i < 32; i += 8)
        dst[(size_t)(bx + y + i) * R + permk32(by + x)] = __float2half_rn(t[x][y + i]);
}

// ---------------------------------------------------------------------------
// FP16 mma.sync GEMM: CTA 128x128, 8 warps (2m x 4n), warp tile 64x32,
// m16n8k16. BK=64, 3-stage cp.async (wait1), ADD-swizzled smem, LDS.128.
// Warp-parity k-half skew + interleaved LDS/MMA to overlap crossbar & tensor.
// EPI 0: C = fp16(gelu(C+bias)) -> g_H (k-permuted cols)
// EPI 1: C = C+bias, fold + residual x -> out (fp32)
// ---------------------------------------------------------------------------
template <int NGL, int K, int EPI>
__global__ __launch_bounds__(256, 2) void mma_gemm_kernel(
        const float* __restrict__ bias,
        const float* __restrict__ x,
        float* __restrict__ out) {
    extern __shared__ char smem[];
    const __half* __restrict__ A  = (EPI == 0) ? g_Y : g_H;
    const __half* __restrict__ Bt = (EPI == 0) ? g_W1T : g_W2T;

    const int tid  = threadIdx.x;
    const int lane = tid & 31;
    const int wid  = tid >> 5;
    const int wm   = wid & 1;
    const int wn   = wid >> 1;
    const int g    = lane >> 2;
    const int tig  = lane & 3;
    const int mBase = blockIdx.y * BM;
    const int nBase = blockIdx.x * BN;

    const uint32_t sbase = smem_u32(smem);

    // cp.async: A 1024 + B 1024 chunks (16B) per stage; 8 per thread
    const int r0 = tid >> 3;       // base row 0..31 (parity const as r += 32)
    const int j0 = tid & 7;        // source chunk within 128B k-row
    const __half* gA0 = A  + (size_t)(mBase + r0) * K + j0 * 8;
    const __half* gB0 = Bt + (size_t)(nBase + r0) * K + j0 * 8;
    const uint32_t dchunk = (uint32_t)((j0 + 4 * (r0 & 1)) & 7);
    const uint32_t dA0 = (uint32_t)r0 * ROWB + dchunk * 16u;

    auto load_stage = [&](int slot, int ks) {
        const uint32_t sb = sbase + (uint32_t)slot * STAGE_BYTES;
        const int ko = ks * BKH;
#pragma unroll
        for (int i = 0; i < 4; ++i)
            cp_async16(sb + dA0 + i * (32u * ROWB), gA0 + (size_t)(32 * i) * K + ko);
#pragma unroll
        for (int i = 0; i < 4; ++i)
            cp_async16(sb + (uint32_t)(BM * ROWB) + dA0 + i * (32u * ROWB),
                       gB0 + (size_t)(32 * i) * K + ko);
        cp_commit();
    };

    float acc[4][4][4];
#pragma unroll
    for (int i = 0; i < 4; ++i)
#pragma unroll
        for (int j = 0; j < 4; ++j)
#pragma unroll
            for (int q = 0; q < 4; ++q) acc[i][j][q] = 0.f;

    // fragment read offsets: phys chunk = (qq*4 + tig + 4*(g&1)) & 7
    const int pa = g & 1;
    uint32_t ckq[2];
#pragma unroll
    for (int qq = 0; qq < 2; ++qq)
        ckq[qq] = (uint32_t)(((qq * 4 + tig + 4 * pa) & 7) * 16);
    const uint32_t aRow0 = (uint32_t)(wm * 64 + g) * ROWB;
    const uint32_t bRow0 = (uint32_t)(BM * ROWB) + (uint32_t)(wn * 32 + g) * ROWB;

    const int qskew = wid & 1;     // odd warps process k-halves in reverse

    constexpr int KT = K / BKH;
    load_stage(0, 0);
    load_stage(1, 1);

    for (int kt = 0; kt < KT; ++kt) {
        if (kt + 1 < KT) cp_wait1(); else cp_wait0();
        __syncthreads();
        if (kt + 2 < KT) load_stage((kt + 2) % NST, kt + 2);

        const char* st = smem + (kt % NST) * STAGE_BYTES;
#pragma unroll
        for (int qi = 0; qi < 2; ++qi) {
            const uint32_t ck = ckq[qi ^ qskew];
            // B fragments + first A fragment
            uint4 bb[4];
#pragma unroll
            for (int nt = 0; nt < 4; ++nt)
                bb[nt] = *(const uint4*)(st + bRow0 + (uint32_t)(nt * 8) * ROWB + ck);
            uint4 alo = *(const uint4*)(st + aRow0 + ck);
            uint4 ahi = *(const uint4*)(st + aRow0 + 8u * ROWB + ck);
#pragma unroll
            for (int mt = 0; mt < 4; ++mt) {
                const uint4 clo = alo, chi = ahi;
                if (mt < 3) {   // prefetch next m-band while current MMAs issue
                    alo = *(const uint4*)(st + aRow0 + (uint32_t)((mt + 1) * 16) * ROWB + ck);
                    ahi = *(const uint4*)(st + aRow0 + (uint32_t)((mt + 1) * 16 + 8) * ROWB + ck);
                }
#pragma unroll
                for (int nt = 0; nt < 4; ++nt) {
                    mma_f16(acc[mt][nt], clo.x, chi.x, clo.y, chi.y, bb[nt].x, bb[nt].y);
                    mma_f16(acc[mt][nt], clo.z, chi.z, clo.w, chi.w, bb[nt].z, bb[nt].w);
                }
            }
        }
    }

    // ---------------- epilogue ----------------
#pragma unroll
    for (int mt = 0; mt < 4; ++mt) {
#pragma unroll
        for (int half = 0; half < 2; ++half) {
            const int row = mBase + wm * 64 + mt * 16 + g + half * 8;
            int bimg = 0, hp = 0, wp = 0;
            if (EPI == 1) {
                bimg = row / 576;
                const int l = row - bimg * 576;
                hp = l / 24;
                wp = l - hp * 24;
            }
#pragma unroll
            for (int nt = 0; nt < 4; ++nt) {
                const int col = nBase + wn * 32 + nt * 8 + 2 * tig;  // logical
                const float c0 = acc[mt][nt][half * 2 + 0];
                const float c1 = acc[mt][nt][half * 2 + 1];
                if (EPI == 0) {
                    float a0 = c0 + __ldg(&bias[col]);
                    float a1 = c1 + __ldg(&bias[col + 1]);
                    a0 = 0.5f * a0 * (1.0f + erff(a0 * 0.70710678118654752f));
                    a1 = 0.5f * a1 * (1.0f + erff(a1 * 0.70710678118654752f));
                    __half2 h2 = __floats2half2_rn(a0, a1);
                    *(__half2*)(g_H + (size_t)row * NGL + permk32(col)) = h2;
                } else {
                    const int cg  = col >> 8;
                    const int rem = col & 255;
                    const int ph  = rem >> 4;
                    const int pw  = rem & 15;
                    const size_t oi = (((size_t)(bimg * 3 + cg) * 384 + hp * 16 + ph) * 384
                                       + wp * 16 + pw);
                    const float2 xv = *(const float2*)(x + oi);
                    float2 v;
                    v.x = xv.x + c0 + __ldg(&bias[col]);
                    v.y = xv.y + c1 + __ldg(&bias[col + 1]);
                    *(float2*)(out + oi) = v;
                }
            }
        }
    }
}

extern "C" void kernel_launch(void* const* d_in, const int* in_sizes, int n_in,
                              void* d_out, int out_size) {
    const float* x    = (const float*)d_in[0];
    const float* ln_w = (const float*)d_in[1];
    const float* ln_b = (const float*)d_in[2];
    const float* w1   = (const float*)d_in[3];
    const float* b1   = (const float*)d_in[4];
    const float* w2   = (const float*)d_in[5];
    const float* b2   = (const float*)d_in[6];
    float* out        = (float*)d_out;

    static bool configured = false;
    if (!configured) {
        cudaFuncSetAttribute(mma_gemm_kernel<HID, PS, 0>,
                             cudaFuncAttributeMaxDynamicSharedMemorySize, SMEM_BYTES);
        cudaFuncSetAttribute(mma_gemm_kernel<PS, HID, 1>,
                             cudaFuncAttributeMaxDynamicSharedMemorySize, SMEM_BYTES);
        configured = true;
    }

    dim3 tb(32, 8);
    transpose_kernel<0><<<dim3(HID / 32, PS / 32), tb>>>(w1, PS, HID);
    transpose_kernel<1><<<dim3(PS / 32, HID / 32), tb>>>(w2, HID, PS);

    patch_ln_kernel<<<TOKENS, 256>>>(x, ln_w, ln_b);

    dim3 g1(HID / BN, TOKENS / BM);   // (12, 288)
    mma_gemm_kernel<HID, PS, 0><<<g1, 256, SMEM_BYTES>>>(b1, nullptr, nullptr);

    dim3 g2(PS / BN, TOKENS / BM);    // (6, 288)
    mma_gemm_kernel<PS, HID, 1><<<g2, 256, SMEM_BYTES>>>(b2, x, out);
}

// round 11
// speedup vs baseline: 1.0617x; 1.0428x over previous
#include <cuda_runtime.h>
#include <cuda_fp16.h>
#include <cstdint>
#include <math.h>

#define TOKENS 36864
#define PS 768
#define HID 1536

#define BM 128
#define BN 128
#define BKH 64                 // K halves per stage (128 B rows)
#define NST 3
#define ROWB 128
#define STAGE_BYTES ((BM + BN) * ROWB)        // 32768
#define SMEM_BYTES (NST * STAGE_BYTES)        // 98304

// Scratch (device globals — allocation guards forbid cudaMalloc)
__device__ __half g_Y[(size_t)TOKENS * PS];     // LN'd patches, fp16, k-permuted
__device__ __half g_H[(size_t)TOKENS * HID];    // hidden acts, fp16, k-permuted
__device__ __half g_W1T[(size_t)HID * PS];      // w1^T [1536,768], k-permuted
__device__ __half g_W2T[(size_t)PS * HID];      // w2^T [768,1536], k-permuted

// k-permutation within 32-blocks: k=(q,h,t,i) -> pos = t*8 + q*4 + h*2 + i
__device__ __forceinline__ int permk32(int k) {
    return (k & ~31) | ((k & 6) << 2) | (((k >> 4) & 1) << 2)
         | (((k >> 3) & 1) << 1) | (k & 1);
}
__device__ __forceinline__ uint32_t smem_u32(const void* p) {
    uint32_t a;
    asm("{ .reg .u64 t; cvta.to.shared.u64 t, %1; cvt.u32.u64 %0, t; }" : "=r"(a) : "l"(p));
    return a;
}
__device__ __forceinline__ void cp_async16(uint32_t dst, const void* src) {
    asm volatile("cp.async.cg.shared.global [%0], [%1], 16;\n" :: "r"(dst), "l"(src));
}
__device__ __forceinline__ void cp_commit() { asm volatile("cp.async.commit_group;\n" ::: "memory"); }
__device__ __forceinline__ void cp_wait1()  { asm volatile("cp.async.wait_group 1;\n" ::: "memory"); }
__device__ __forceinline__ void cp_wait0()  { asm volatile("cp.async.wait_group 0;\n" ::: "memory"); }

__device__ __forceinline__ void mma_f16(float* d, uint32_t a0, uint32_t a1,
                                        uint32_t a2, uint32_t a3,
                                        uint32_t b0, uint32_t b1) {
    asm volatile(
        "mma.sync.aligned.m16n8k16.row.col.f32.f16.f16.f32 "
        "{%0,%1,%2,%3}, {%4,%5,%6,%7}, {%8,%9}, {%0,%1,%2,%3};"
        : "+f"(d[0]), "+f"(d[1]), "+f"(d[2]), "+f"(d[3])
        : "r"(a0), "r"(a1), "r"(a2), "r"(a3), "r"(b0), "r"(b1));
}

// Fast exact GELU: 0.5x(1+erf(x/sqrt2)), erf via A&S 7.1.26 (|err|<=1.5e-7)
__device__ __forceinline__ float gelu_fast(float v) {
    const float z = fabsf(v) * 0.70710678118654752f;
    const float t = __fdividef(1.0f, fmaf(0.3275911f, z, 1.0f));
    float p = fmaf(t, 1.061405429f, -1.453152027f);
    p = fmaf(t, p, 1.421413741f);
    p = fmaf(t, p, -0.284496736f);
    p = fmaf(t, p, 0.254829592f);
    p *= t;
    const float e = __expf(-z * z);
    const float erfa = fmaf(-p, e, 1.0f);          // erf(|z|)
    const float erfv = copysignf(erfa, v);
    return 0.5f * v * (1.0f + erfv);
}

// ---------------------------------------------------------------------------
// Kernel 1: unfold + LayerNorm -> fp16, k-permuted
// ---------------------------------------------------------------------------
__global__ void patch_ln_kernel(const float* __restrict__ x,
                                const float* __restrict__ ln_w,
                                const float* __restrict__ ln_b) {
    const int token = blockIdx.x;
    const int b  = token / 576;
    const int l  = token - b * 576;
    const int hp = l / 24;
    const int wp = l - hp * 24;
    const int t  = threadIdx.x;

    float v[3];
#pragma unroll
    for (int i = 0; i < 3; ++i) {
        const int p   = t + i * 256;
        const int c   = p >> 8;
        const int rem = p & 255;
        const int ph  = rem >> 4;
        const int pw  = rem & 15;
        const int xi  = ((b * 3 + c) * 384 + hp * 16 + ph) * 384 + wp * 16 + pw;
        v[i] = x[xi];
    }
    float s  = v[0] + v[1] + v[2];
    float sq = v[0] * v[0] + v[1] * v[1] + v[2] * v[2];
#pragma unroll
    for (int o = 16; o > 0; o >>= 1) {
        s  += __shfl_xor_sync(0xffffffffu, s, o);
        sq += __shfl_xor_sync(0xffffffffu, sq, o);
    }
    __shared__ float red_s[8], red_q[8];
    const int warp = t >> 5, lane = t & 31;
    if (lane == 0) { red_s[warp] = s; red_q[warp] = sq; }
    __syncthreads();
    float tot = 0.f, totq = 0.f;
#pragma unroll
    for (int i = 0; i < 8; ++i) { tot += red_s[i]; totq += red_q[i]; }
    const float mu  = tot * (1.0f / 768.0f);
    const float var = totq * (1.0f / 768.0f) - mu * mu;
    const float inv = rsqrtf(var + 1e-5f);

    __half* yrow = g_Y + (size_t)token * PS;
#pragma unroll
    for (int i = 0; i < 3; ++i) {
        const int p = t + i * 256;
        yrow[permk32(p)] = __float2half_rn((v[i] - mu) * inv * ln_w[p] + ln_b[p]);
    }
}

// ---------------------------------------------------------------------------
// Transpose: src [R,C] fp32 -> dst [C,R] fp16, K dim (rows of dst) permuted
// ---------------------------------------------------------------------------
template <int WHICH>
__global__ void transpose_kernel(const float* __restrict__ src, int R, int C) {
    __half* __restrict__ dst = (WHICH == 0) ? g_W1T : g_W2T;
    __shared__ float t[32][33];
    const int bx = blockIdx.x * 32, by = blockIdx.y * 32;
    const int x = threadIdx.x, y = threadIdx.y;
#pragma unroll
    for (int i = 0; i < 32; i += 8)
        t[y + i][x] = src[(size_t)(by + y + i) * C + bx + x];
    __syncthreads();
#pragma unroll
    for (int i = 0; i < 32; i += 8)
        dst[(size_t)(bx + y + i) * R + permk32(by + x)] = __float2half_rn(t[x][y + i]);
}

// ---------------------------------------------------------------------------
// FP16 mma.sync GEMM: CTA 128x128, 8 warps (2m x 4n), warp tile 64x32,
// m16n8k16. BK=64, 3-stage cp.async (wait1), ADD-swizzled smem, LDS.128.
// EPI 0: C = fp16(gelu(C+bias)) -> g_H (k-permuted cols)
// EPI 1: C = C+bias, fold + residual x -> out (fp32)
// ---------------------------------------------------------------------------
template <int NGL, int K, int EPI>
__global__ __launch_bounds__(256, 2) void mma_gemm_kernel(
        const float* __restrict__ bias,
        const float* __restrict__ x,
        float* __restrict__ out) {
    extern __shared__ char smem[];
    const __half* __restrict__ A  = (EPI == 0) ? g_Y : g_H;
    const __half* __restrict__ Bt = (EPI == 0) ? g_W1T : g_W2T;

    const int tid  = threadIdx.x;
    const int lane = tid & 31;
    const int wid  = tid >> 5;
    const int wm   = wid & 1;
    const int wn   = wid >> 1;
    const int g    = lane >> 2;
    const int tig  = lane & 3;
    const int mBase = blockIdx.y * BM;
    const int nBase = blockIdx.x * BN;

    const uint32_t sbase = smem_u32(smem);

    // cp.async: A 1024 + B 1024 chunks (16B) per stage; 8 per thread
    const int r0 = tid >> 3;       // base row 0..31 (parity const as r += 32)
    const int j0 = tid & 7;        // source chunk within 128B k-row
    const __half* gA0 = A  + (size_t)(mBase + r0) * K + j0 * 8;
    const __half* gB0 = Bt + (size_t)(nBase + r0) * K + j0 * 8;
    const uint32_t dchunk = (uint32_t)((j0 + 4 * (r0 & 1)) & 7);
    const uint32_t dA0 = (uint32_t)r0 * ROWB + dchunk * 16u;

    auto load_stage = [&](int slot, int ks) {
        const uint32_t sb = sbase + (uint32_t)slot * STAGE_BYTES;
        const int ko = ks * BKH;
#pragma unroll
        for (int i = 0; i < 4; ++i)
            cp_async16(sb + dA0 + i * (32u * ROWB), gA0 + (size_t)(32 * i) * K + ko);
#pragma unroll
        for (int i = 0; i < 4; ++i)
            cp_async16(sb + (uint32_t)(BM * ROWB) + dA0 + i * (32u * ROWB),
                       gB0 + (size_t)(32 * i) * K + ko);
        cp_commit();
    };

    float acc[4][4][4];
#pragma unroll
    for (int i = 0; i < 4; ++i)
#pragma unroll
        for (int j = 0; j < 4; ++j)
#pragma unroll
            for (int q = 0; q < 4; ++q) acc[i][j][q] = 0.f;

    // fragment read offsets: phys chunk = (qq*4 + tig + 4*(g&1)) & 7
    const int pa = g & 1;
    uint32_t ckq[2];
#pragma unroll
    for (int qq = 0; qq < 2; ++qq)
        ckq[qq] = (uint32_t)(((qq * 4 + tig + 4 * pa) & 7) * 16);
    const uint32_t aRow0 = (uint32_t)(wm * 64 + g) * ROWB;
    const uint32_t bRow0 = (uint32_t)(BM * ROWB) + (uint32_t)(wn * 32 + g) * ROWB;

    constexpr int KT = K / BKH;
    load_stage(0, 0);
    load_stage(1, 1);

    for (int kt = 0; kt < KT; ++kt) {
        if (kt + 1 < KT) cp_wait1(); else cp_wait0();
        __syncthreads();
        if (kt + 2 < KT) load_stage((kt + 2) % NST, kt + 2);

        const char* st = smem + (kt % NST) * STAGE_BYTES;
#pragma unroll
        for (int qq = 0; qq < 2; ++qq) {
            uint4 alo[4], ahi[4], bb[4];
#pragma unroll
            for (int mt = 0; mt < 4; ++mt) {
                alo[mt] = *(const uint4*)(st + aRow0 + (uint32_t)(mt * 16) * ROWB + ckq[qq]);
                ahi[mt] = *(const uint4*)(st + aRow0 + (uint32_t)(mt * 16 + 8) * ROWB + ckq[qq]);
            }
#pragma unroll
            for (int nt = 0; nt < 4; ++nt)
                bb[nt] = *(const uint4*)(st + bRow0 + (uint32_t)(nt * 8) * ROWB + ckq[qq]);
#pragma unroll
            for (int mt = 0; mt < 4; ++mt)
#pragma unroll
                for (int nt = 0; nt < 4; ++nt) {
                    mma_f16(acc[mt][nt], alo[mt].x, ahi[mt].x, alo[mt].y, ahi[mt].y,
                            bb[nt].x, bb[nt].y);
                    mma_f16(acc[mt][nt], alo[mt].z, ahi[mt].z, alo[mt].w, ahi[mt].w,
                            bb[nt].z, bb[nt].w);
                }
        }
    }

    // ---------------- epilogue ----------------
#pragma unroll
    for (int mt = 0; mt < 4; ++mt) {
#pragma unroll
        for (int half = 0; half < 2; ++half) {
            const int row = mBase + wm * 64 + mt * 16 + g + half * 8;
            int bimg = 0, hp = 0, wp = 0;
            if (EPI == 1) {
                bimg = row / 576;
                const int l = row - bimg * 576;
                hp = l / 24;
                wp = l - hp * 24;
            }
#pragma unroll
            for (int nt = 0; nt < 4; ++nt) {
                const int col = nBase + wn * 32 + nt * 8 + 2 * tig;  // logical
                const float c0 = acc[mt][nt][half * 2 + 0];
                const float c1 = acc[mt][nt][half * 2 + 1];
                if (EPI == 0) {
                    const float a0 = gelu_fast(c0 + __ldg(&bias[col]));
                    const float a1 = gelu_fast(c1 + __ldg(&bias[col + 1]));
                    __half2 h2 = __floats2half2_rn(a0, a1);
                    *(__half2*)(g_H + (size_t)row * NGL + permk32(col)) = h2;
                } else {
                    const int cg  = col >> 8;
                    const int rem = col & 255;
                    const int ph  = rem >> 4;
                    const int pw  = rem & 15;
                    const size_t oi = (((size_t)(bimg * 3 + cg) * 384 + hp * 16 + ph) * 384
                                       + wp * 16 + pw);
                    const float2 xv = *(const float2*)(x + oi);
                    float2 v;
                    v.x = xv.x + c0 + __ldg(&bias[col]);
                    v.y = xv.y + c1 + __ldg(&bias[col + 1]);
                    *(float2*)(out + oi) = v;
                }
            }
        }
    }
}

extern "C" void kernel_launch(void* const* d_in, const int* in_sizes, int n_in,
                              void* d_out, int out_size) {
    const float* x    = (const float*)d_in[0];
    const float* ln_w = (const float*)d_in[1];
    const float* ln_b = (const float*)d_in[2];
    const float* w1   = (const float*)d_in[3];
    const float* b1   = (const float*)d_in[4];
    const float* w2   = (const float*)d_in[5];
    const float* b2   = (const float*)d_in[6];
    float* out        = (float*)d_out;

    static bool configured = false;
    if (!configured) {
        cudaFuncSetAttribute(mma_gemm_kernel<HID, PS, 0>,
                             cudaFuncAttributeMaxDynamicSharedMemorySize, SMEM_BYTES);
        cudaFuncSetAttribute(mma_gemm_kernel<PS, HID, 1>,
                             cudaFuncAttributeMaxDynamicSharedMemorySize, SMEM_BYTES);
        configured = true;
    }

    dim3 tb(32, 8);
    transpose_kernel<0><<<dim3(HID / 32, PS / 32), tb>>>(w1, PS, HID);
    transpose_kernel<1><<<dim3(PS / 32, HID / 32), tb>>>(w2, HID, PS);

    patch_ln_kernel<<<TOKENS, 256>>>(x, ln_w, ln_b);

    dim3 g1(HID / BN, TOKENS / BM);   // (12, 288)
    mma_gemm_kernel<HID, PS, 0><<<g1, 256, SMEM_BYTES>>>(b1, nullptr, nullptr);

    dim3 g2(PS / BN, TOKENS / BM);    // (6, 288)
    mma_gemm_kernel<PS, HID, 1><<<g2, 256, SMEM_BYTES>>>(b2, x, out);
}

// round 12
// speedup vs baseline: 1.0674x; 1.0053x over previous
#include <cuda_runtime.h>
#include <cuda_fp16.h>
#include <cstdint>
#include <math.h>

#define TOKENS 36864
#define PS 768
#define HID 1536

#define BM 128
#define BN 128
#define BKH 64                 // K halves per stage (128 B rows)
#define NST 3
#define ROWB 128
#define STAGE_BYTES ((BM + BN) * ROWB)        // 32768
#define MBAR_OFF (NST * STAGE_BYTES)          // 98304
#define SMEM_BYTES (MBAR_OFF + 64)

// Scratch (device globals — allocation guards forbid cudaMalloc)
__device__ __half g_Y[(size_t)TOKENS * PS];     // LN'd patches, fp16, k-permuted
__device__ __half g_H[(size_t)TOKENS * HID];    // hidden acts, fp16, k-permuted
__device__ __half g_W1T[(size_t)HID * PS];      // w1^T [1536,768], k-permuted
__device__ __half g_W2T[(size_t)PS * HID];      // w2^T [768,1536], k-permuted

// k-permutation within 32-blocks: k=(q,h,t,i) -> pos = t*8 + q*4 + h*2 + i
__device__ __forceinline__ int permk32(int k) {
    return (k & ~31) | ((k & 6) << 2) | (((k >> 4) & 1) << 2)
         | (((k >> 3) & 1) << 1) | (k & 1);
}
__device__ __forceinline__ uint32_t smem_u32(const void* p) {
    uint32_t a;
    asm("{ .reg .u64 t; cvta.to.shared.u64 t, %1; cvt.u32.u64 %0, t; }" : "=r"(a) : "l"(p));
    return a;
}
__device__ __forceinline__ void cp_async16(uint32_t dst, const void* src) {
    asm volatile("cp.async.cg.shared.global [%0], [%1], 16;\n" :: "r"(dst), "l"(src));
}
// .noinc: counts this thread's arrival when its outstanding cp.asyncs complete
// (the R10 bug was the non-.noinc form: it increments expect-count first, net 0)
__device__ __forceinline__ void cp_mbar_arrive_noinc(uint32_t mbar) {
    asm volatile("cp.async.mbarrier.arrive.noinc.shared::cta.b64 [%0];" :: "r"(mbar) : "memory");
}
__device__ __forceinline__ void mbar_init(uint32_t mbar, uint32_t cnt) {
    asm volatile("mbarrier.init.shared::cta.b64 [%0], %1;" :: "r"(mbar), "r"(cnt) : "memory");
}
__device__ __forceinline__ void mbar_arrive(uint32_t mbar) {
    asm volatile("mbarrier.arrive.shared::cta.b64 _, [%0];" :: "r"(mbar) : "memory");
}
__device__ __forceinline__ void mbar_wait(uint32_t mbar, uint32_t parity) {
    uint32_t done;
    asm volatile(
        "{\n\t.reg .pred p;\n\t"
        "mbarrier.try_wait.parity.acquire.cta.shared::cta.b64 p, [%1], %2;\n\t"
        "selp.b32 %0, 1, 0, p;\n\t}"
        : "=r"(done) : "r"(mbar), "r"(parity) : "memory");
    if (!done) {
        asm volatile(
            "{\n\t.reg .pred P1;\n"
            "WL_%=:\n\t"
            "mbarrier.try_wait.parity.acquire.cta.shared::cta.b64 P1, [%0], %1, 0x989680;\n\t"
            "@P1 bra.uni WD_%=;\n\t"
            "bra.uni WL_%=;\n"
            "WD_%=:\n\t}"
            :: "r"(mbar), "r"(parity) : "memory");
    }
}

__device__ __forceinline__ void mma_f16(float* d, uint32_t a0, uint32_t a1,
                                        uint32_t a2, uint32_t a3,
                                        uint32_t b0, uint32_t b1) {
    asm volatile(
        "mma.sync.aligned.m16n8k16.row.col.f32.f16.f16.f32 "
        "{%0,%1,%2,%3}, {%4,%5,%6,%7}, {%8,%9}, {%0,%1,%2,%3};"
        : "+f"(d[0]), "+f"(d[1]), "+f"(d[2]), "+f"(d[3])
        : "r"(a0), "r"(a1), "r"(a2), "r"(a3), "r"(b0), "r"(b1));
}

// Fast exact GELU: 0.5x(1+erf(x/sqrt2)), erf via A&S 7.1.26 (|err|<=1.5e-7)
__device__ __forceinline__ float gelu_fast(float v) {
    const float z = fabsf(v) * 0.70710678118654752f;
    const float t = __fdividef(1.0f, fmaf(0.3275911f, z, 1.0f));
    float p = fmaf(t, 1.061405429f, -1.453152027f);
    p = fmaf(t, p, 1.421413741f);
    p = fmaf(t, p, -0.284496736f);
    p = fmaf(t, p, 0.254829592f);
    p *= t;
    const float e = __expf(-z * z);
    const float erfa = fmaf(-p, e, 1.0f);
    const float erfv = copysignf(erfa, v);
    return 0.5f * v * (1.0f + erfv);
}

// ---------------------------------------------------------------------------
// Kernel 1: unfold + LayerNorm -> fp16, k-permuted
// ---------------------------------------------------------------------------
__global__ void patch_ln_kernel(const float* __restrict__ x,
                                const float* __restrict__ ln_w,
                                const float* __restrict__ ln_b) {
    const int token = blockIdx.x;
    const int b  = token / 576;
    const int l  = token - b * 576;
    const int hp = l / 24;
    const int wp = l - hp * 24;
    const int t  = threadIdx.x;

    float v[3];
#pragma unroll
    for (int i = 0; i < 3; ++i) {
        const int p   = t + i * 256;
        const int c   = p >> 8;
        const int rem = p & 255;
        const int ph  = rem >> 4;
        const int pw  = rem & 15;
        const int xi  = ((b * 3 + c) * 384 + hp * 16 + ph) * 384 + wp * 16 + pw;
        v[i] = x[xi];
    }
    float s  = v[0] + v[1] + v[2];
    float sq = v[0] * v[0] + v[1] * v[1] + v[2] * v[2];
#pragma unroll
    for (int o = 16; o > 0; o >>= 1) {
        s  += __shfl_xor_sync(0xffffffffu, s, o);
        sq += __shfl_xor_sync(0xffffffffu, sq, o);
    }
    __shared__ float red_s[8], red_q[8];
    const int warp = t >> 5, lane = t & 31;
    if (lane == 0) { red_s[warp] = s; red_q[warp] = sq; }
    __syncthreads();
    float tot = 0.f, totq = 0.f;
#pragma unroll
    for (int i = 0; i < 8; ++i) { tot += red_s[i]; totq += red_q[i]; }
    const float mu  = tot * (1.0f / 768.0f);
    const float var = totq * (1.0f / 768.0f) - mu * mu;
    const float inv = rsqrtf(var + 1e-5f);

    __half* yrow = g_Y + (size_t)token * PS;
#pragma unroll
    for (int i = 0; i < 3; ++i) {
        const int p = t + i * 256;
        yrow[permk32(p)] = __float2half_rn((v[i] - mu) * inv * ln_w[p] + ln_b[p]);
    }
}

// ---------------------------------------------------------------------------
// Transpose: src [R,C] fp32 -> dst [C,R] fp16, K dim (rows of dst) permuted
// ---------------------------------------------------------------------------
template <int WHICH>
__global__ void transpose_kernel(const float* __restrict__ src, int R, int C) {
    __half* __restrict__ dst = (WHICH == 0) ? g_W1T : g_W2T;
    __shared__ float t[32][33];
    const int bx = blockIdx.x * 32, by = blockIdx.y * 32;
    const int x = threadIdx.x, y = threadIdx.y;
#pragma unroll
    for (int i = 0; i < 32; i += 8)
        t[y + i][x] = src[(size_t)(by + y + i) * C + bx + x];
    __syncthreads();
#pragma unroll
    for (int i = 0; i < 32; i += 8)
        dst[(size_t)(bx + y + i) * R + permk32(by + x)] = __float2half_rn(t[x][y + i]);
}

// ---------------------------------------------------------------------------
// FP16 mma.sync GEMM: CTA 128x128, 8 warps (2m x 4n), warp tile 64x32,
// m16n8k16, BK=64. 3-stage pipeline with per-stage mbarriers (no block
// barrier in mainloop): full[s] (256 cp.async.noinc arrivals), cons[s]
// (8 warp arrivals). Warps run phase-decoupled.
// EPI 0: C = fp16(gelu(C+bias)) -> g_H (k-permuted cols)
// EPI 1: C = C+bias, fold + residual x -> out (fp32)
// ---------------------------------------------------------------------------
template <int NGL, int K, int EPI>
__global__ __launch_bounds__(256, 2) void mma_gemm_kernel(
        const float* __restrict__ bias,
        const float* __restrict__ x,
        float* __restrict__ out) {
    extern __shared__ char smem[];
    const __half* __restrict__ A  = (EPI == 0) ? g_Y : g_H;
    const __half* __restrict__ Bt = (EPI == 0) ? g_W1T : g_W2T;

    const int tid  = threadIdx.x;
    const int lane = tid & 31;
    const int wid  = tid >> 5;
    const int wm   = wid & 1;
    const int wn   = wid >> 1;
    const int g    = lane >> 2;
    const int tig  = lane & 3;
    const int mBase = blockIdx.y * BM;
    const int nBase = blockIdx.x * BN;

    const uint32_t sbase = smem_u32(smem);
    const uint32_t mb    = sbase + MBAR_OFF;   // full[s]=mb+s*16, cons[s]=mb+s*16+8

    if (tid == 0) {
#pragma unroll
        for (int s = 0; s < NST; ++s) {
            mbar_init(mb + s * 16, 256);
            mbar_init(mb + s * 16 + 8, 8);
        }
    }
    __syncthreads();

    // cp.async: A 1024 + B 1024 chunks (16B) per stage; 8 per thread
    const int r0 = tid >> 3;
    const int j0 = tid & 7;
    const __half* gA0 = A  + (size_t)(mBase + r0) * K + j0 * 8;
    const __half* gB0 = Bt + (size_t)(nBase + r0) * K + j0 * 8;
    const uint32_t dchunk = (uint32_t)((j0 + 4 * (r0 & 1)) & 7);
    const uint32_t dA0 = (uint32_t)r0 * ROWB + dchunk * 16u;

    auto load_stage = [&](int slot, int ks) {
        const uint32_t sb = sbase + (uint32_t)slot * STAGE_BYTES;
        const int ko = ks * BKH;
#pragma unroll
        for (int i = 0; i < 4; ++i)
            cp_async16(sb + dA0 + i * (32u * ROWB), gA0 + (size_t)(32 * i) * K + ko);
#pragma unroll
        for (int i = 0; i < 4; ++i)
            cp_async16(sb + (uint32_t)(BM * ROWB) + dA0 + i * (32u * ROWB),
                       gB0 + (size_t)(32 * i) * K + ko);
        cp_mbar_arrive_noinc(mb + (uint32_t)slot * 16);
    };

    float acc[4][4][4];
#pragma unroll
    for (int i = 0; i < 4; ++i)
#pragma unroll
        for (int j = 0; j < 4; ++j)
#pragma unroll
            for (int q = 0; q < 4; ++q) acc[i][j][q] = 0.f;

    // fragment read offsets: phys chunk = (qq*4 + tig + 4*(g&1)) & 7
    const int pa = g & 1;
    uint32_t ckq[2];
#pragma unroll
    for (int qq = 0; qq < 2; ++qq)
        ckq[qq] = (uint32_t)(((qq * 4 + tig + 4 * pa) & 7) * 16);
    const uint32_t aRow0 = (uint32_t)(wm * 64 + g) * ROWB;
    const uint32_t bRow0 = (uint32_t)(BM * ROWB) + (uint32_t)(wn * 32 + g) * ROWB;

    constexpr int KT = K / BKH;
    // prologue: fill stages 0, 1
    load_stage(0, 0);
    load_stage(1, 1);

    int s = 0, pPar = 0;       // consume stage / parity
    int sl = 2, plPar = 0;     // producer slot / parity

    for (int kt = 0; kt < KT; ++kt) {
        const int kl = kt + 2;
        if (kl < KT) {
            if (kt >= 1) mbar_wait(mb + (uint32_t)sl * 16 + 8, (uint32_t)(plPar ^ 1));
            load_stage(sl, kl);
            if (sl == NST - 1) { sl = 0; plPar ^= 1; } else { ++sl; }
        }

        mbar_wait(mb + (uint32_t)s * 16, (uint32_t)pPar);

        const char* st = smem + s * STAGE_BYTES;
#pragma unroll
        for (int qq = 0; qq < 2; ++qq) {
            uint4 alo[4], ahi[4], bb[4];
#pragma unroll
            for (int mt = 0; mt < 4; ++mt) {
                alo[mt] = *(const uint4*)(st + aRow0 + (uint32_t)(mt * 16) * ROWB + ckq[qq]);
                ahi[mt] = *(const uint4*)(st + aRow0 + (uint32_t)(mt * 16 + 8) * ROWB + ckq[qq]);
            }
#pragma unroll
            for (int nt = 0; nt < 4; ++nt)
                bb[nt] = *(const uint4*)(st + bRow0 + (uint32_t)(nt * 8) * ROWB + ckq[qq]);
#pragma unroll
            for (int mt = 0; mt < 4; ++mt)
#pragma unroll
                for (int nt = 0; nt < 4; ++nt) {
                    mma_f16(acc[mt][nt], alo[mt].x, ahi[mt].x, alo[mt].y, ahi[mt].y,
                            bb[nt].x, bb[nt].y);
                    mma_f16(acc[mt][nt], alo[mt].z, ahi[mt].z, alo[mt].w, ahi[mt].w,
                            bb[nt].z, bb[nt].w);
                }
        }

        if (lane == 0) mbar_arrive(mb + (uint32_t)s * 16 + 8);
        if (s == NST - 1) { s = 0; pPar ^= 1; } else { ++s; }
    }

    // ---------------- epilogue ----------------
#pragma unroll
    for (int mt = 0; mt < 4; ++mt) {
#pragma unroll
        for (int half = 0; half < 2; ++half) {
            const int row = mBase + wm * 64 + mt * 16 + g + half * 8;
            int bimg = 0, hp = 0, wp = 0;
            if (EPI == 1) {
                bimg = row / 576;
                const int l = row - bimg * 576;
                hp = l / 24;
                wp = l - hp * 24;
            }
#pragma unroll
            for (int nt = 0; nt < 4; ++nt) {
                const int col = nBase + wn * 32 + nt * 8 + 2 * tig;  // logical
                const float c0 = acc[mt][nt][half * 2 + 0];
                const float c1 = acc[mt][nt][half * 2 + 1];
                if (EPI == 0) {
                    const float a0 = gelu_fast(c0 + __ldg(&bias[col]));
                    const float a1 = gelu_fast(c1 + __ldg(&bias[col + 1]));
                    __half2 h2 = __floats2half2_rn(a0, a1);
                    *(__half2*)(g_H + (size_t)row * NGL + permk32(col)) = h2;
                } else {
                    const int cg  = col >> 8;
                    const int rem = col & 255;
                    const int ph  = rem >> 4;
                    const int pw  = rem & 15;
                    const size_t oi = (((size_t)(bimg * 3 + cg) * 384 + hp * 16 + ph) * 384
                                       + wp * 16 + pw);
                    const float2 xv = *(const float2*)(x + oi);
                    float2 v;
                    v.x = xv.x + c0 + __ldg(&bias[col]);
                    v.y = xv.y + c1 + __ldg(&bias[col + 1]);
                    *(float2*)(out + oi) = v;
                }
            }
        }
    }
}

extern "C" void kernel_launch(void* const* d_in, const int* in_sizes, int n_in,
                              void* d_out, int out_size) {
    const float* x    = (const float*)d_in[0];
    const float* ln_w = (const float*)d_in[1];
    const float* ln_b = (const float*)d_in[2];
    const float* w1   = (const float*)d_in[3];
    const float* b1   = (const float*)d_in[4];
    const float* w2   = (const float*)d_in[5];
    const float* b2   = (const float*)d_in[6];
    float* out        = (float*)d_out;

    static bool configured = false;
    if (!configured) {
        cudaFuncSetAttribute(mma_gemm_kernel<HID, PS, 0>,
                             cudaFuncAttributeMaxDynamicSharedMemorySize, SMEM_BYTES);
        cudaFuncSetAttribute(mma_gemm_kernel<PS, HID, 1>,
                             cudaFuncAttributeMaxDynamicSharedMemorySize, SMEM_BYTES);
        configured = true;
    }

    dim3 tb(32, 8);
    transpose_kernel<0><<<dim3(HID / 32, PS / 32), tb>>>(w1, PS, HID);
    transpose_kernel<1><<<dim3(PS / 32, HID / 32), tb>>>(w2, HID, PS);

    patch_ln_kernel<<<TOKENS, 256>>>(x, ln_w, ln_b);

    dim3 g1(HID / BN, TOKENS / BM);   // (12, 288)
    mma_gemm_kernel<HID, PS, 0><<<g1, 256, SMEM_BYTES>>>(b1, nullptr, nullptr);

    dim3 g2(PS / BN, TOKENS / BM);    // (6, 288)
    mma_gemm_kernel<PS, HID, 1><<<g2, 256, SMEM_BYTES>>>(b2, x, out);
}

// round 13
// speedup vs baseline: 1.0692x; 1.0018x over previous
#include <cuda_runtime.h>
#include <cuda_fp16.h>
#include <cstdint>
#include <math.h>

#define TOKENS 36864
#define PS 768
#define HID 1536

#define BM 128
#define BN 128
#define BKH 64                 // K halves per stage (128 B rows)
#define NST 3
#define ROWB 128
#define STAGE_BYTES ((BM + BN) * ROWB)        // 32768
#define SMEM_BYTES (NST * STAGE_BYTES)        // 98304
#define GTHREADS 128           // 4 warps per CTA, warp tile 64x64 (2m x 2n)

// Scratch (device globals — allocation guards forbid cudaMalloc)
__device__ __half g_Y[(size_t)TOKENS * PS];     // LN'd patches, fp16, k-permuted
__device__ __half g_H[(size_t)TOKENS * HID];    // hidden acts, fp16, k-permuted
__device__ __half g_W1T[(size_t)HID * PS];      // w1^T [1536,768], k-permuted
__device__ __half g_W2T[(size_t)PS * HID];      // w2^T [768,1536], k-permuted

// k-permutation within 32-blocks: k=(q,h,t,i) -> pos = t*8 + q*4 + h*2 + i
__device__ __forceinline__ int permk32(int k) {
    return (k & ~31) | ((k & 6) << 2) | (((k >> 4) & 1) << 2)
         | (((k >> 3) & 1) << 1) | (k & 1);
}
__device__ __forceinline__ uint32_t smem_u32(const void* p) {
    uint32_t a;
    asm("{ .reg .u64 t; cvta.to.shared.u64 t, %1; cvt.u32.u64 %0, t; }" : "=r"(a) : "l"(p));
    return a;
}
__device__ __forceinline__ void cp_async16(uint32_t dst, const void* src) {
    asm volatile("cp.async.cg.shared.global [%0], [%1], 16;\n" :: "r"(dst), "l"(src));
}
__device__ __forceinline__ void cp_commit() { asm volatile("cp.async.commit_group;\n" ::: "memory"); }
__device__ __forceinline__ void cp_wait1()  { asm volatile("cp.async.wait_group 1;\n" ::: "memory"); }
__device__ __forceinline__ void cp_wait0()  { asm volatile("cp.async.wait_group 0;\n" ::: "memory"); }

__device__ __forceinline__ void mma_f16(float* d, uint32_t a0, uint32_t a1,
                                        uint32_t a2, uint32_t a3,
                                        uint32_t b0, uint32_t b1) {
    asm volatile(
        "mma.sync.aligned.m16n8k16.row.col.f32.f16.f16.f32 "
        "{%0,%1,%2,%3}, {%4,%5,%6,%7}, {%8,%9}, {%0,%1,%2,%3};"
        : "+f"(d[0]), "+f"(d[1]), "+f"(d[2]), "+f"(d[3])
        : "r"(a0), "r"(a1), "r"(a2), "r"(a3), "r"(b0), "r"(b1));
}

// Fast exact GELU: 0.5x(1+erf(x/sqrt2)), erf via A&S 7.1.26 (|err|<=1.5e-7)
__device__ __forceinline__ float gelu_fast(float v) {
    const float z = fabsf(v) * 0.70710678118654752f;
    const float t = __fdividef(1.0f, fmaf(0.3275911f, z, 1.0f));
    float p = fmaf(t, 1.061405429f, -1.453152027f);
    p = fmaf(t, p, 1.421413741f);
    p = fmaf(t, p, -0.284496736f);
    p = fmaf(t, p, 0.254829592f);
    p *= t;
    const float e = __expf(-z * z);
    const float erfa = fmaf(-p, e, 1.0f);
    const float erfv = copysignf(erfa, v);
    return 0.5f * v * (1.0f + erfv);
}

// ---------------------------------------------------------------------------
// Kernel 1: unfold + LayerNorm -> fp16, k-permuted
// ---------------------------------------------------------------------------
__global__ void patch_ln_kernel(const float* __restrict__ x,
                                const float* __restrict__ ln_w,
                                const float* __restrict__ ln_b) {
    const int token = blockIdx.x;
    const int b  = token / 576;
    const int l  = token - b * 576;
    const int hp = l / 24;
    const int wp = l - hp * 24;
    const int t  = threadIdx.x;

    float v[3];
#pragma unroll
    for (int i = 0; i < 3; ++i) {
        const int p   = t + i * 256;
        const int c   = p >> 8;
        const int rem = p & 255;
        const int ph  = rem >> 4;
        const int pw  = rem & 15;
        const int xi  = ((b * 3 + c) * 384 + hp * 16 + ph) * 384 + wp * 16 + pw;
        v[i] = x[xi];
    }
    float s  = v[0] + v[1] + v[2];
    float sq = v[0] * v[0] + v[1] * v[1] + v[2] * v[2];
#pragma unroll
    for (int o = 16; o > 0; o >>= 1) {
        s  += __shfl_xor_sync(0xffffffffu, s, o);
        sq += __shfl_xor_sync(0xffffffffu, sq, o);
    }
    __shared__ float red_s[8], red_q[8];
    const int warp = t >> 5, lane = t & 31;
    if (lane == 0) { red_s[warp] = s; red_q[warp] = sq; }
    __syncthreads();
    float tot = 0.f, totq = 0.f;
#pragma unroll
    for (int i = 0; i < 8; ++i) { tot += red_s[i]; totq += red_q[i]; }
    const float mu  = tot * (1.0f / 768.0f);
    const float var = totq * (1.0f / 768.0f) - mu * mu;
    const float inv = rsqrtf(var + 1e-5f);

    __half* yrow = g_Y + (size_t)token * PS;
#pragma unroll
    for (int i = 0; i < 3; ++i) {
        const int p = t + i * 256;
        yrow[permk32(p)] = __float2half_rn((v[i] - mu) * inv * ln_w[p] + ln_b[p]);
    }
}

// ---------------------------------------------------------------------------
// Transpose: src [R,C] fp32 -> dst [C,R] fp16, K dim (rows of dst) permuted
// ---------------------------------------------------------------------------
template <int WHICH>
__global__ void transpose_kernel(const float* __restrict__ src, int R, int C) {
    __half* __restrict__ dst = (WHICH == 0) ? g_W1T : g_W2T;
    __shared__ float t[32][33];
    const int bx = blockIdx.x * 32, by = blockIdx.y * 32;
    const int x = threadIdx.x, y = threadIdx.y;
#pragma unroll
    for (int i = 0; i < 32; i += 8)
        t[y + i][x] = src[(size_t)(by + y + i) * C + bx + x];
    __syncthreads();
#pragma unroll
    for (int i = 0; i < 32; i += 8)
        dst[(size_t)(bx + y + i) * R + permk32(by + x)] = __float2half_rn(t[x][y + i]);
}

// ---------------------------------------------------------------------------
// FP16 mma.sync GEMM: CTA 128x128, 4 warps (2m x 2n), warp tile 64x64,
// m16n8k16, BK=64, 3-stage cp.async (wait1), ADD-swizzled smem, LDS.128.
// 128-thread CTAs -> 2 CTAs/SM with up to 256 regs/thread (no spill at ~220).
// Halves A-fragment crossbar amplification (2 n-warp cols instead of 4).
// EPI 0: C = fp16(gelu(C+bias)) -> g_H (k-permuted cols)
// EPI 1: C = C+bias, fold + residual x -> out (fp32)
// ---------------------------------------------------------------------------
template <int NGL, int K, int EPI>
__global__ __launch_bounds__(GTHREADS, 2) void mma_gemm_kernel(
        const float* __restrict__ bias,
        const float* __restrict__ x,
        float* __restrict__ out) {
    extern __shared__ char smem[];
    const __half* __restrict__ A  = (EPI == 0) ? g_Y : g_H;
    const __half* __restrict__ Bt = (EPI == 0) ? g_W1T : g_W2T;

    const int tid  = threadIdx.x;
    const int lane = tid & 31;
    const int wid  = tid >> 5;
    const int wm   = wid & 1;        // 0..1 -> 64-row band
    const int wn   = wid >> 1;       // 0..1 -> 64-col band
    const int g    = lane >> 2;
    const int tig  = lane & 3;
    const int mBase = blockIdx.y * BM;
    const int nBase = blockIdx.x * BN;

    const uint32_t sbase = smem_u32(smem);

    // cp.async: A 1024 + B 1024 chunks (16B) per stage; 16 per thread
    const int r0 = tid >> 3;       // base row 0..15 (row parity const: +16i)
    const int j0 = tid & 7;        // source chunk within 128B k-row
    const __half* gA0 = A  + (size_t)(mBase + r0) * K + j0 * 8;
    const __half* gB0 = Bt + (size_t)(nBase + r0) * K + j0 * 8;
    const uint32_t dchunk = (uint32_t)((j0 + 4 * (r0 & 1)) & 7);
    const uint32_t dA0 = (uint32_t)r0 * ROWB + dchunk * 16u;

    auto load_stage = [&](int slot, int ks) {
        const uint32_t sb = sbase + (uint32_t)slot * STAGE_BYTES;
        const int ko = ks * BKH;
#pragma unroll
        for (int i = 0; i < 8; ++i)
            cp_async16(sb + dA0 + i * (16u * ROWB), gA0 + (size_t)(16 * i) * K + ko);
#pragma unroll
        for (int i = 0; i < 8; ++i)
            cp_async16(sb + (uint32_t)(BM * ROWB) + dA0 + i * (16u * ROWB),
                       gB0 + (size_t)(16 * i) * K + ko);
        cp_commit();
    };

    float acc[4][8][4];
#pragma unroll
    for (int i = 0; i < 4; ++i)
#pragma unroll
        for (int j = 0; j < 8; ++j)
#pragma unroll
            for (int q = 0; q < 4; ++q) acc[i][j][q] = 0.f;

    // fragment read offsets: phys chunk = (qq*4 + tig + 4*(g&1)) & 7
    const int pa = g & 1;
    uint32_t ckq[2];
#pragma unroll
    for (int qq = 0; qq < 2; ++qq)
        ckq[qq] = (uint32_t)(((qq * 4 + tig + 4 * pa) & 7) * 16);
    const uint32_t aRow0 = (uint32_t)(wm * 64 + g) * ROWB;
    const uint32_t bRow0 = (uint32_t)(BM * ROWB) + (uint32_t)(wn * 64 + g) * ROWB;

    constexpr int KT = K / BKH;
    load_stage(0, 0);
    load_stage(1, 1);

    for (int kt = 0; kt < KT; ++kt) {
        if (kt + 1 < KT) cp_wait1(); else cp_wait0();
        __syncthreads();
        if (kt + 2 < KT) load_stage((kt + 2) % NST, kt + 2);

        const char* st = smem + (kt % NST) * STAGE_BYTES;
#pragma unroll
        for (int qq = 0; qq < 2; ++qq) {
            uint4 alo[4], ahi[4], bb[8];
#pragma unroll
            for (int mt = 0; mt < 4; ++mt) {
                alo[mt] = *(const uint4*)(st + aRow0 + (uint32_t)(mt * 16) * ROWB + ckq[qq]);
                ahi[mt] = *(const uint4*)(st + aRow0 + (uint32_t)(mt * 16 + 8) * ROWB + ckq[qq]);
            }
#pragma unroll
            for (int nt = 0; nt < 8; ++nt)
                bb[nt] = *(const uint4*)(st + bRow0 + (uint32_t)(nt * 8) * ROWB + ckq[qq]);
#pragma unroll
            for (int mt = 0; mt < 4; ++mt)
#pragma unroll
                for (int nt = 0; nt < 8; ++nt) {
                    mma_f16(acc[mt][nt], alo[mt].x, ahi[mt].x, alo[mt].y, ahi[mt].y,
                            bb[nt].x, bb[nt].y);
                    mma_f16(acc[mt][nt], alo[mt].z, ahi[mt].z, alo[mt].w, ahi[mt].w,
                            bb[nt].z, bb[nt].w);
                }
        }
    }

    // ---------------- epilogue ----------------
#pragma unroll
    for (int mt = 0; mt < 4; ++mt) {
#pragma unroll
        for (int half = 0; half < 2; ++half) {
            const int row = mBase + wm * 64 + mt * 16 + g + half * 8;
            int bimg = 0, hp = 0, wp = 0;
            if (EPI == 1) {
                bimg = row / 576;
                const int l = row - bimg * 576;
                hp = l / 24;
                wp = l - hp * 24;
            }
#pragma unroll
            for (int nt = 0; nt < 8; ++nt) {
                const int col = nBase + wn * 64 + nt * 8 + 2 * tig;  // logical
                const float c0 = acc[mt][nt][half * 2 + 0];
                const float c1 = acc[mt][nt][half * 2 + 1];
                if (EPI == 0) {
                    const float a0 = gelu_fast(c0 + __ldg(&bias[col]));
                    const float a1 = gelu_fast(c1 + __ldg(&bias[col + 1]));
                    __half2 h2 = __floats2half2_rn(a0, a1);
                    *(__half2*)(g_H + (size_t)row * NGL + permk32(col)) = h2;
                } else {
                    const int cg  = col >> 8;
                    const int rem = col & 255;
                    const int ph  = rem >> 4;
                    const int pw  = rem & 15;
                    const size_t oi = (((size_t)(bimg * 3 + cg) * 384 + hp * 16 + ph) * 384
                                       + wp * 16 + pw);
                    const float2 xv = *(const float2*)(x + oi);
                    float2 v;
                    v.x = xv.x + c0 + __ldg(&bias[col]);
                    v.y = xv.y + c1 + __ldg(&bias[col + 1]);
                    *(float2*)(out + oi) = v;
                }
            }
        }
    }
}

extern "C" void kernel_launch(void* const* d_in, const int* in_sizes, int n_in,
                              void* d_out, int out_size) {
    const float* x    = (const float*)d_in[0];
    const float* ln_w = (const float*)d_in[1];
    const float* ln_b = (const float*)d_in[2];
    const float* w1   = (const float*)d_in[3];
    const float* b1   = (const float*)d_in[4];
    const float* w2   = (const float*)d_in[5];
    const float* b2   = (const float*)d_in[6];
    float* out        = (float*)d_out;

    static bool configured = false;
    if (!configured) {
        cudaFuncSetAttribute(mma_gemm_kernel<HID, PS, 0>,
                             cudaFuncAttributeMaxDynamicSharedMemorySize, SMEM_BYTES);
        cudaFuncSetAttribute(mma_gemm_kernel<PS, HID, 1>,
                             cudaFuncAttributeMaxDynamicSharedMemorySize, SMEM_BYTES);
        configured = true;
    }

    dim3 tb(32, 8);
    transpose_kernel<0><<<dim3(HID / 32, PS / 32), tb>>>(w1, PS, HID);
    transpose_kernel<1><<<dim3(PS / 32, HID / 32), tb>>>(w2, HID, PS);

    patch_ln_kernel<<<TOKENS, 256>>>(x, ln_w, ln_b);

    dim3 g1(HID / BN, TOKENS / BM);   // (12, 288)
    mma_gemm_kernel<HID, PS, 0><<<g1, GTHREADS, SMEM_BYTES>>>(b1, nullptr, nullptr);

    dim3 g2(PS / BN, TOKENS / BM);    // (6, 288)
    mma_gemm_kernel<PS, HID, 1><<<g2, GTHREADS, SMEM_BYTES>>>(b2, x, out);
}

// round 14
// speedup vs baseline: 1.0774x; 1.0076x over previous
#include <cuda_runtime.h>
#include <cuda_fp16.h>
#include <cstdint>
#include <math.h>

#define TOKENS 36864
#define PS 768
#define HID 1536

#define BM 128
#define BN 128
#define BKH 64                 // K halves per stage (128 B rows)
#define NST 3
#define ROWB 128
#define STAGE_BYTES ((BM + BN) * ROWB)        // 32768
#define SMEM_BYTES (NST * STAGE_BYTES)        // 98304
#define GTHREADS 128           // 4 warps per CTA, warp tile 64x64 (2m x 2n)

// Scratch (device globals — allocation guards forbid cudaMalloc)
__device__ __half g_Y[(size_t)TOKENS * PS];     // LN'd patches, fp16, k-permuted
__device__ __half g_H[(size_t)TOKENS * HID];    // hidden acts, fp16, k-permuted
__device__ __half g_W1T[(size_t)HID * PS];      // w1^T [1536,768], k-permuted
__device__ __half g_W2T[(size_t)PS * HID];      // w2^T [768,1536], k-permuted

// k-permutation within 32-blocks: k=(q,h,t,i) -> pos = t*8 + q*4 + h*2 + i
__device__ __forceinline__ int permk32(int k) {
    return (k & ~31) | ((k & 6) << 2) | (((k >> 4) & 1) << 2)
         | (((k >> 3) & 1) << 1) | (k & 1);
}
__device__ __forceinline__ uint32_t smem_u32(const void* p) {
    uint32_t a;
    asm("{ .reg .u64 t; cvta.to.shared.u64 t, %1; cvt.u32.u64 %0, t; }" : "=r"(a) : "l"(p));
    return a;
}
__device__ __forceinline__ void cp_async16(uint32_t dst, const void* src) {
    asm volatile("cp.async.cg.shared.global [%0], [%1], 16;\n" :: "r"(dst), "l"(src));
}
__device__ __forceinline__ void cp_commit() { asm volatile("cp.async.commit_group;\n" ::: "memory"); }
__device__ __forceinline__ void cp_wait1()  { asm volatile("cp.async.wait_group 1;\n" ::: "memory"); }
__device__ __forceinline__ void cp_wait0()  { asm volatile("cp.async.wait_group 0;\n" ::: "memory"); }

__device__ __forceinline__ void mma_f16(float* d, uint32_t a0, uint32_t a1,
                                        uint32_t a2, uint32_t a3,
                                        uint32_t b0, uint32_t b1) {
    asm volatile(
        "mma.sync.aligned.m16n8k16.row.col.f32.f16.f16.f32 "
        "{%0,%1,%2,%3}, {%4,%5,%6,%7}, {%8,%9}, {%0,%1,%2,%3};"
        : "+f"(d[0]), "+f"(d[1]), "+f"(d[2]), "+f"(d[3])
        : "r"(a0), "r"(a1), "r"(a2), "r"(a3), "r"(b0), "r"(b1));
}

// Fast exact GELU: 0.5x(1+erf(x/sqrt2)), erf via A&S 7.1.26 (|err|<=1.5e-7)
__device__ __forceinline__ float gelu_fast(float v) {
    const float z = fabsf(v) * 0.70710678118654752f;
    const float t = __fdividef(1.0f, fmaf(0.3275911f, z, 1.0f));
    float p = fmaf(t, 1.061405429f, -1.453152027f);
    p = fmaf(t, p, 1.421413741f);
    p = fmaf(t, p, -0.284496736f);
    p = fmaf(t, p, 0.254829592f);
    p *= t;
    const float e = __expf(-z * z);
    const float erfa = fmaf(-p, e, 1.0f);
    const float erfv = copysignf(erfa, v);
    return 0.5f * v * (1.0f + erfv);
}

// ---------------------------------------------------------------------------
// Kernel 1: unfold + LayerNorm -> fp16, k-permuted
// ---------------------------------------------------------------------------
__global__ void patch_ln_kernel(const float* __restrict__ x,
                                const float* __restrict__ ln_w,
                                const float* __restrict__ ln_b) {
    const int token = blockIdx.x;
    const int b  = token / 576;
    const int l  = token - b * 576;
    const int hp = l / 24;
    const int wp = l - hp * 24;
    const int t  = threadIdx.x;

    float v[3];
#pragma unroll
    for (int i = 0; i < 3; ++i) {
        const int p   = t + i * 256;
        const int c   = p >> 8;
        const int rem = p & 255;
        const int ph  = rem >> 4;
        const int pw  = rem & 15;
        const int xi  = ((b * 3 + c) * 384 + hp * 16 + ph) * 384 + wp * 16 + pw;
        v[i] = x[xi];
    }
    float s  = v[0] + v[1] + v[2];
    float sq = v[0] * v[0] + v[1] * v[1] + v[2] * v[2];
#pragma unroll
    for (int o = 16; o > 0; o >>= 1) {
        s  += __shfl_xor_sync(0xffffffffu, s, o);
        sq += __shfl_xor_sync(0xffffffffu, sq, o);
    }
    __shared__ float red_s[8], red_q[8];
    const int warp = t >> 5, lane = t & 31;
    if (lane == 0) { red_s[warp] = s; red_q[warp] = sq; }
    __syncthreads();
    float tot = 0.f, totq = 0.f;
#pragma unroll
    for (int i = 0; i < 8; ++i) { tot += red_s[i]; totq += red_q[i]; }
    const float mu  = tot * (1.0f / 768.0f);
    const float var = totq * (1.0f / 768.0f) - mu * mu;
    const float inv = rsqrtf(var + 1e-5f);

    __half* yrow = g_Y + (size_t)token * PS;
#pragma unroll
    for (int i = 0; i < 3; ++i) {
        const int p = t + i * 256;
        yrow[permk32(p)] = __float2half_rn((v[i] - mu) * inv * ln_w[p] + ln_b[p]);
    }
}

// ---------------------------------------------------------------------------
// Transpose: src [R,C] fp32 -> dst [C,R] fp16, K dim (rows of dst) permuted
// ---------------------------------------------------------------------------
template <int WHICH>
__global__ void transpose_kernel(const float* __restrict__ src, int R, int C) {
    __half* __restrict__ dst = (WHICH == 0) ? g_W1T : g_W2T;
    __shared__ float t[32][33];
    const int bx = blockIdx.x * 32, by = blockIdx.y * 32;
    const int x = threadIdx.x, y = threadIdx.y;
#pragma unroll
    for (int i = 0; i < 32; i += 8)
        t[y + i][x] = src[(size_t)(by + y + i) * C + bx + x];
    __syncthreads();
#pragma unroll
    for (int i = 0; i < 32; i += 8)
        dst[(size_t)(bx + y + i) * R + permk32(by + x)] = __float2half_rn(t[x][y + i]);
}

// ---------------------------------------------------------------------------
// FP16 mma.sync GEMM: CTA 128x128, 4 warps (2m x 2n), warp tile 64x64,
// m16n8k16, BK=64, 3-stage cp.async (wait1), ADD-swizzled smem, LDS.128.
// 128-thread CTAs -> 2 CTAs/SM, 256-reg budget. Epilogue invariants hoisted.
// EPI 0: C = fp16(gelu(C+bias)) -> g_H (k-permuted cols)
// EPI 1: C = C+bias, fold + residual x -> out (fp32)
// ---------------------------------------------------------------------------
template <int NGL, int K, int EPI>
__global__ __launch_bounds__(GTHREADS, 2) void mma_gemm_kernel(
        const float* __restrict__ bias,
        const float* __restrict__ x,
        float* __restrict__ out) {
    extern __shared__ char smem[];
    const __half* __restrict__ A  = (EPI == 0) ? g_Y : g_H;
    const __half* __restrict__ Bt = (EPI == 0) ? g_W1T : g_W2T;

    const int tid  = threadIdx.x;
    const int lane = tid & 31;
    const int wid  = tid >> 5;
    const int wm   = wid & 1;        // 0..1 -> 64-row band
    const int wn   = wid >> 1;       // 0..1 -> 64-col band
    const int g    = lane >> 2;
    const int tig  = lane & 3;
    const int mBase = blockIdx.y * BM;
    const int nBase = blockIdx.x * BN;

    const uint32_t sbase = smem_u32(smem);

    // cp.async: A 1024 + B 1024 chunks (16B) per stage; 16 per thread
    const int r0 = tid >> 3;       // base row 0..15 (row parity const: +16i)
    const int j0 = tid & 7;        // source chunk within 128B k-row
    const __half* gA0 = A  + (size_t)(mBase + r0) * K + j0 * 8;
    const __half* gB0 = Bt + (size_t)(nBase + r0) * K + j0 * 8;
    const uint32_t dchunk = (uint32_t)((j0 + 4 * (r0 & 1)) & 7);
    const uint32_t dA0 = (uint32_t)r0 * ROWB + dchunk * 16u;

    auto load_stage = [&](int slot, int ks) {
        const uint32_t sb = sbase + (uint32_t)slot * STAGE_BYTES;
        const int ko = ks * BKH;
#pragma unroll
        for (int i = 0; i < 8; ++i)
            cp_async16(sb + dA0 + i * (16u * ROWB), gA0 + (size_t)(16 * i) * K + ko);
#pragma unroll
        for (int i = 0; i < 8; ++i)
            cp_async16(sb + (uint32_t)(BM * ROWB) + dA0 + i * (16u * ROWB),
                       gB0 + (size_t)(16 * i) * K + ko);
        cp_commit();
    };

    float acc[4][8][4];
#pragma unroll
    for (int i = 0; i < 4; ++i)
#pragma unroll
        for (int j = 0; j < 8; ++j)
#pragma unroll
            for (int q = 0; q < 4; ++q) acc[i][j][q] = 0.f;

    // fragment read offsets: phys chunk = (qq*4 + tig + 4*(g&1)) & 7
    const int pa = g & 1;
    uint32_t ckq[2];
#pragma unroll
    for (int qq = 0; qq < 2; ++qq)
        ckq[qq] = (uint32_t)(((qq * 4 + tig + 4 * pa) & 7) * 16);
    const uint32_t aRow0 = (uint32_t)(wm * 64 + g) * ROWB;
    const uint32_t bRow0 = (uint32_t)(BM * ROWB) + (uint32_t)(wn * 64 + g) * ROWB;

    constexpr int KT = K / BKH;
    load_stage(0, 0);
    load_stage(1, 1);

    for (int kt = 0; kt < KT; ++kt) {
        if (kt + 1 < KT) cp_wait1(); else cp_wait0();
        __syncthreads();
        if (kt + 2 < KT) load_stage((kt + 2) % NST, kt + 2);

        const char* st = smem + (kt % NST) * STAGE_BYTES;
#pragma unroll
        for (int qq = 0; qq < 2; ++qq) {
            uint4 alo[4], ahi[4], bb[8];
#pragma unroll
            for (int mt = 0; mt < 4; ++mt) {
                alo[mt] = *(const uint4*)(st + aRow0 + (uint32_t)(mt * 16) * ROWB + ckq[qq]);
                ahi[mt] = *(const uint4*)(st + aRow0 + (uint32_t)(mt * 16 + 8) * ROWB + ckq[qq]);
            }
#pragma unroll
            for (int nt = 0; nt < 8; ++nt)
                bb[nt] = *(const uint4*)(st + bRow0 + (uint32_t)(nt * 8) * ROWB + ckq[qq]);
#pragma unroll
            for (int mt = 0; mt < 4; ++mt)
#pragma unroll
                for (int nt = 0; nt < 8; ++nt) {
                    mma_f16(acc[mt][nt], alo[mt].x, ahi[mt].x, alo[mt].y, ahi[mt].y,
                            bb[nt].x, bb[nt].y);
                    mma_f16(acc[mt][nt], alo[mt].z, ahi[mt].z, alo[mt].w, ahi[mt].w,
                            bb[nt].z, bb[nt].w);
                }
        }
    }

    // ---------------- epilogue (per-nt invariants hoisted) ----------------
    int    pcol[8];      // EPI0: permuted col; EPI1: image col offset
    float2 bv[8];
#pragma unroll
    for (int nt = 0; nt < 8; ++nt) {
        const int col = nBase + wn * 64 + nt * 8 + 2 * tig;
        bv[nt] = make_float2(__ldg(&bias[col]), __ldg(&bias[col + 1]));
        if (EPI == 0) {
            pcol[nt] = permk32(col);
        } else {
            const int cg  = col >> 8;
            const int rem = col & 255;
            const int ph  = rem >> 4;
            const int pw  = rem & 15;
            pcol[nt] = cg * 147456 + ph * 384 + pw;
        }
    }
    // row band is 64-aligned and 576 = 9*64 -> bimg constant per warp
    const int rowބ = mBase + wm * 64;                 // band base
    const int bimg = rowބ / 576;
    const int lb   = rowބ - bimg * 576;               // band offset in image

#pragma unroll
    for (int mt = 0; mt < 4; ++mt) {
#pragma unroll
        for (int half = 0; half < 2; ++half) {
            const int row = rowބ + mt * 16 + g + half * 8;
            if (EPI == 0) {
                __half* hrow = g_H + (size_t)row * NGL;
#pragma unroll
                for (int nt = 0; nt < 8; ++nt) {
                    const float a0 = gelu_fast(acc[mt][nt][half * 2 + 0] + bv[nt].x);
                    const float a1 = gelu_fast(acc[mt][nt][half * 2 + 1] + bv[nt].y);
                    *(__half2*)(hrow + pcol[nt]) = __floats2half2_rn(a0, a1);
                }
            } else {
                const int l  = lb + mt * 16 + g + half * 8;
                const int hp = l / 24;
                const int wp = l - hp * 24;
                const size_t rowOff = (size_t)bimg * 442368 + hp * 6144 + wp * 16;
#pragma unroll
                for (int nt = 0; nt < 8; ++nt) {
                    const size_t oi = rowOff + (size_t)pcol[nt];
                    const float2 xv = *(const float2*)(x + oi);
                    float2 v;
                    v.x = xv.x + acc[mt][nt][half * 2 + 0] + bv[nt].x;
                    v.y = xv.y + acc[mt][nt][half * 2 + 1] + bv[nt].y;
                    *(float2*)(out + oi) = v;
                }
            }
        }
    }
}

extern "C" void kernel_launch(void* const* d_in, const int* in_sizes, int n_in,
                              void* d_out, int out_size) {
    const float* x    = (const float*)d_in[0];
    const float* ln_w = (const float*)d_in[1];
    const float* ln_b = (const float*)d_in[2];
    const float* w1   = (const float*)d_in[3];
    const float* b1   = (const float*)d_in[4];
    const float* w2   = (const float*)d_in[5];
    const float* b2   = (const float*)d_in[6];
    float* out        = (float*)d_out;

    static bool configured = false;
    if (!configured) {
        cudaFuncSetAttribute(mma_gemm_kernel<HID, PS, 0>,
                             cudaFuncAttributeMaxDynamicSharedMemorySize, SMEM_BYTES);
        cudaFuncSetAttribute(mma_gemm_kernel<PS, HID, 1>,
                             cudaFuncAttributeMaxDynamicSharedMemorySize, SMEM_BYTES);
        configured = true;
    }

    dim3 tb(32, 8);
    transpose_kernel<0><<<dim3(HID / 32, PS / 32), tb>>>(w1, PS, HID);
    transpose_kernel<1><<<dim3(PS / 32, HID / 32), tb>>>(w2, HID, PS);

    patch_ln_kernel<<<TOKENS, 256>>>(x, ln_w, ln_b);

    dim3 g1(HID / BN, TOKENS / BM);   // (12, 288)
    mma_gemm_kernel<HID, PS, 0><<<g1, GTHREADS, SMEM_BYTES>>>(b1, nullptr, nullptr);

    dim3 g2(PS / BN, TOKENS / BM);    // (6, 288)
    mma_gemm_kernel<PS, HID, 1><<<g2, GTHREADS, SMEM_BYTES>>>(b2, x, out);
}